// round 2
// baseline (speedup 1.0000x reference)
#include <cuda_runtime.h>
#include <math.h>

#define B_ 32
#define S_ 64
#define T_ 16
#define U_ 1024
#define E_ 256
#define V_ 20200
#define G_ 3072   /* 3*U */

// ---------------- device scratch (static globals; no runtime alloc) ----------------
__device__ float d_xemb[(S_*B_)*E_];        // [s*32+b][256]
__device__ float d_gxall[S_*B_*G_];         // [s][b][3072]  (x@Wx + b_in, all steps)
__device__ float d_hbuf[2][B_*U_];          // ping-pong hidden
__device__ float d_enc[B_*S_*U_];           // encoded [b][s][u]
__device__ float d_pre[B_*S_*U_];           // W1(encoded)+b1 [b][s][u]
__device__ float d_gpart[5][B_*G_];         // split-K partials for h@Wh / x@dec_Wx
__device__ float d_qpart[8][B_*U_];         // split-K partials for dec_h@W2
__device__ float d_xcat[B_*(U_+E_)];        // [ctx, Ed[tok]] per step
__device__ float d_Hall[T_*B_*U_];          // decoder hidden states, rows t*32+b
__device__ float d_logits_alt[T_*B_*V_];    // logits scratch (preds-only output case)

// ---------------- embedding gather ----------------
__global__ void embed_src(const int* __restrict__ enc_in, const float* __restrict__ Ee) {
    int idx = blockIdx.x * 256 + threadIdx.x;     // 2048*256 total
    int r = idx >> 8, e = idx & 255;
    int s = r >> 5, b = r & 31;
    d_xemb[r * E_ + e] = Ee[(size_t)enc_in[b * S_ + s] * E_ + e];
}

// ---------------- generic fp32 tiled GEMM ----------------
// MODE 0: C[M,N] = A@B + bias (N multiple of BN)
// MODE 1: logits epilogue: row gm=(t*32+b) -> out row (b*16+t); N bounds-checked; +bias
// MODE 2: split-K partial: blockIdx.z covers K chunk [z*Kc, (z+1)*Kc), writes C + z*M*N, no bias
template<int BM, int BN, int BK, int TM, int TN, int MODE>
__global__ void gemm_k(const float* __restrict__ A, const float* __restrict__ B,
                       const float* __restrict__ bias, float* __restrict__ C,
                       int M, int N, int K, int Kc)
{
    static_assert(TM == 4 && TN == 4, "micro tile fixed at 4x4");
    constexpr int TX = BN / TN, TY = BM / TM, NT = TX * TY;
    __shared__ float As[BK][BM];
    __shared__ float Bs[BK][BN];

    const int tid = threadIdx.x;
    const int tx = tid % TX, ty = tid / TX;
    const int n0 = blockIdx.x * BN;
    const int m0 = blockIdx.y * BM;

    int k0 = 0, k1 = K;
    float* Cp = C;
    if (MODE == 2) { k0 = blockIdx.z * Kc; k1 = k0 + Kc; Cp = C + (size_t)blockIdx.z * M * N; }

    float acc[TM][TN];
#pragma unroll
    for (int i = 0; i < TM; i++)
#pragma unroll
        for (int j = 0; j < TN; j++) acc[i][j] = 0.f;

    for (int kt = k0; kt < k1; kt += BK) {
#pragma unroll
        for (int i = tid; i < BM * BK; i += NT) {
            int m = i / BK, k = i % BK;
            As[k][m] = A[(size_t)(m0 + m) * K + kt + k];
        }
#pragma unroll
        for (int i = tid; i < BK * BN; i += NT) {
            int k = i / BN, n = i % BN;
            int gn = n0 + n;
            float v = 0.f;
            if (MODE != 1 || gn < N) v = B[(size_t)(kt + k) * N + gn];
            Bs[k][n] = v;
        }
        __syncthreads();
#pragma unroll
        for (int kk = 0; kk < BK; kk++) {
            const float4 av = *reinterpret_cast<const float4*>(&As[kk][ty * TM]);
            const float4 bvv = *reinterpret_cast<const float4*>(&Bs[kk][tx * TN]);
            const float a[4] = {av.x, av.y, av.z, av.w};
            const float bb[4] = {bvv.x, bvv.y, bvv.z, bvv.w};
#pragma unroll
            for (int i = 0; i < TM; i++)
#pragma unroll
                for (int j = 0; j < TN; j++) acc[i][j] += a[i] * bb[j];
        }
        __syncthreads();
    }

#pragma unroll
    for (int i = 0; i < TM; i++) {
        const int gm = m0 + ty * TM + i;
#pragma unroll
        for (int j = 0; j < TN; j++) {
            const int gn = n0 + tx * TN + j;
            if (MODE == 0) {
                Cp[(size_t)gm * N + gn] = acc[i][j] + bias[gn];
            } else if (MODE == 1) {
                if (gn < N) {
                    int bb_ = gm & 31, tt_ = gm >> 5;           // gm = t*32+b
                    Cp[(size_t)(bb_ * T_ + tt_) * N + gn] = acc[i][j] + bias[gn];
                }
            } else {
                Cp[(size_t)gm * N + gn] = acc[i][j];
            }
        }
    }
}

// ---------------- GRU gate: encoder (reduce split-K partials of h@Wh) ----------------
__global__ void gru_gate_enc(const float* __restrict__ gx, const float* __restrict__ b_rec,
                             const float* __restrict__ h_in, float* __restrict__ h_out, int s)
{
    int idx = blockIdx.x * blockDim.x + threadIdx.x;   // 32768
    int b = idx >> 10, u = idx & 1023;
    const float* g = gx + (size_t)b * G_;
    float xz = g[u], xr = g[U_ + u], xc = g[2 * U_ + u];
    float hz = b_rec[u], hr = b_rec[U_ + u], hc = b_rec[2 * U_ + u];
#pragma unroll
    for (int ks = 0; ks < 4; ks++) {
        const float* gp = d_gpart[ks] + (size_t)b * G_;
        hz += gp[u]; hr += gp[U_ + u]; hc += gp[2 * U_ + u];
    }
    float z = 1.f / (1.f + expf(-(xz + hz)));
    float r = 1.f / (1.f + expf(-(xr + hr)));
    float c = tanhf(xc + r * hc);
    float h = z * h_in[idx] + (1.f - z) * c;
    h_out[idx] = h;
    d_enc[(size_t)b * (S_ * U_) + s * U_ + u] = h;
}

// ---------------- GRU gate: decoder (h0 = 0 -> gh = b_rec; h_new = (1-z)*c) ----------------
__global__ void gru_gate_dec(const float* __restrict__ b_in, const float* __restrict__ b_rec,
                             float* __restrict__ h_out, int t)
{
    int idx = blockIdx.x * blockDim.x + threadIdx.x;
    int b = idx >> 10, u = idx & 1023;
    float xz = b_in[u], xr = b_in[U_ + u], xc = b_in[2 * U_ + u];
#pragma unroll
    for (int ks = 0; ks < 5; ks++) {
        const float* gp = d_gpart[ks] + (size_t)b * G_;
        xz += gp[u]; xr += gp[U_ + u]; xc += gp[2 * U_ + u];
    }
    float hz = b_rec[u], hr = b_rec[U_ + u], hc = b_rec[2 * U_ + u];
    float z = 1.f / (1.f + expf(-(xz + hz)));
    float r = 1.f / (1.f + expf(-(xr + hr)));
    float c = tanhf(xc + r * hc);
    float h = (1.f - z) * c;
    h_out[idx] = h;
    d_Hall[(size_t)t * (B_ * U_) + idx] = h;
}

// ---------------- attention + context + embed concat (block per batch row) ----------------
__global__ void attn_ctx(const float* __restrict__ b2, const float* __restrict__ Va,
                         const float* __restrict__ bvp, const float* __restrict__ Ed,
                         const int* __restrict__ teacher, int t)
{
    const int b = blockIdx.x, tid = threadIdx.x;
    __shared__ float qs[U_];
    __shared__ float sc[S_];
    __shared__ float inv_s;

    for (int u = tid; u < U_; u += 256) {
        float v = b2[u];
#pragma unroll
        for (int ks = 0; ks < 8; ks++) v += d_qpart[ks][(size_t)b * U_ + u];
        qs[u] = v;
    }
    __syncthreads();

    const int w = tid >> 5, lane = tid & 31;
    for (int s = w; s < S_; s += 8) {
        const float* pr = d_pre + (size_t)b * (S_ * U_) + (size_t)s * U_;
        float p = 0.f;
        for (int u = lane; u < U_; u += 32) p += tanhf(pr[u] + qs[u]) * Va[u];
#pragma unroll
        for (int o = 16; o > 0; o >>= 1) p += __shfl_xor_sync(0xffffffffu, p, o);
        if (lane == 0) sc[s] = p + bvp[0];
    }
    __syncthreads();

    if (tid == 0) {
        float m = sc[0];
        for (int s = 1; s < S_; s++) m = fmaxf(m, sc[s]);
        float sum = 0.f;
        for (int s = 0; s < S_; s++) { float e = expf(sc[s] - m); sc[s] = e; sum += e; }
        inv_s = 1.f / sum;
    }
    __syncthreads();

    const float inv = inv_s;
    for (int u = tid; u < U_; u += 256) {
        float acc = 0.f;
        const float* eb = d_enc + (size_t)b * (S_ * U_) + u;
#pragma unroll 8
        for (int s = 0; s < S_; s++) acc += sc[s] * eb[(size_t)s * U_];
        d_xcat[(size_t)b * (U_ + E_) + u] = acc * inv;
    }
    const int tok = teacher[b * T_ + t];
    if (tid < E_) d_xcat[(size_t)b * (U_ + E_) + U_ + tid] = Ed[(size_t)tok * E_ + tid];
}

// ---------------- argmax (first-max tie rule, matches jnp.argmax) ----------------
__global__ void argmax_k(const float* __restrict__ logits, long long* outI, float* outF, int asFloat)
{
    const int row = blockIdx.x;          // row = b*16+t over logits [b][t][v]
    const float* p = logits + (size_t)row * V_;
    const int tid = threadIdx.x;
    float best = -INFINITY; int bi = 0;
    for (int v = tid; v < V_; v += 256) {
        float val = p[v];
        if (val > best) { best = val; bi = v; }
    }
    __shared__ float bvs[256]; __shared__ int bis[256];
    bvs[tid] = best; bis[tid] = bi;
    __syncthreads();
    for (int st = 128; st > 0; st >>= 1) {
        if (tid < st) {
            float ov = bvs[tid + st]; int oi = bis[tid + st];
            if (ov > bvs[tid] || (ov == bvs[tid] && oi < bis[tid])) { bvs[tid] = ov; bis[tid] = oi; }
        }
        __syncthreads();
    }
    if (tid == 0) {
        if (asFloat) outF[row] = (float)bis[0];
        else         outI[row] = (long long)bis[0];
    }
}

// ---------------- launcher ----------------
static float* symaddr(const void* sym) {
    void* p = nullptr;
    cudaGetSymbolAddress(&p, sym);
    return (float*)p;
}

extern "C" void kernel_launch(void* const* d_in, const int* in_sizes, int n_in,
                              void* d_out, int out_size)
{
    const int s0 = (n_in >= 22) ? 4 : 2;   // index of Ee (scalars may be omitted)
    const int*   enc_in  = (const int*)d_in[0];
    const int*   teacher = (const int*)d_in[1];
    const float* Ee      = (const float*)d_in[s0 + 0];
    const float* eWx     = (const float*)d_in[s0 + 1];
    const float* eWh     = (const float*)d_in[s0 + 2];
    const float* eb_in   = (const float*)d_in[s0 + 3];
    const float* eb_rec  = (const float*)d_in[s0 + 4];
    const float* Ed      = (const float*)d_in[s0 + 5];
    const float* dWx     = (const float*)d_in[s0 + 6];
    /* dec_Wh (s0+7) is multiplied by h0=0 -> unused */
    const float* db_in   = (const float*)d_in[s0 + 8];
    const float* db_rec  = (const float*)d_in[s0 + 9];
    const float* W1      = (const float*)d_in[s0 + 10];
    const float* b1      = (const float*)d_in[s0 + 11];
    const float* W2      = (const float*)d_in[s0 + 12];
    const float* b2      = (const float*)d_in[s0 + 13];
    const float* Va      = (const float*)d_in[s0 + 14];
    const float* bvp     = (const float*)d_in[s0 + 15];
    const float* Wf      = (const float*)d_in[s0 + 16];
    const float* bf      = (const float*)d_in[s0 + 17];

    float* xemb  = symaddr(d_xemb);
    float* gxall = symaddr(d_gxall);
    float* hbase = symaddr(d_hbuf);
    float* encp  = symaddr(d_enc);
    float* prep  = symaddr(d_pre);
    float* gpart = symaddr(d_gpart);
    float* qpart = symaddr(d_qpart);
    float* xcat  = symaddr(d_xcat);
    float* Hall  = symaddr(d_Hall);
    float* lalt  = symaddr(d_logits_alt);

    // output convention
    const long long LOGN = (long long)B_ * T_ * V_;   // 10,342,400
    float* logits_dst = (float*)d_out;
    long long* predI = nullptr; float* predF = nullptr; int asFloat = 0;
    if ((long long)out_size == LOGN + 512) { predF = (float*)d_out + LOGN; asFloat = 1; }
    else if ((long long)out_size == LOGN + 1024) { predI = (long long*)((float*)d_out + LOGN); }
    else if (out_size == 512) { logits_dst = lalt; predI = (long long*)d_out; }
    // else: logits only

    // h0 = 0
    cudaMemsetAsync(hbase, 0, (size_t)B_ * U_ * sizeof(float));

    // encoder: embed + gx for all steps at once
    embed_src<<<2048, 256>>>(enc_in, Ee);
    gemm_k<64,64,16,4,4,0><<<dim3(G_/64, (S_*B_)/64), 256>>>(xemb, eWx, eb_in, gxall,
                                                             S_*B_, G_, E_, 0);
    // encoder recurrence (64 serial steps): split-K h@Wh + gate
    for (int s = 0; s < S_; s++) {
        float* hin  = hbase + (size_t)(s & 1) * B_ * U_;
        float* hout = hbase + (size_t)((s + 1) & 1) * B_ * U_;
        gemm_k<32,64,16,4,4,2><<<dim3(G_/64, 1, 4), 128>>>(hin, eWh, nullptr, gpart,
                                                           B_, G_, U_, U_/4);
        gru_gate_enc<<<128, 256>>>(gxall + (size_t)s * B_ * G_, eb_rec, hin, hout, s);
    }

    // pre_enc = encoded @ W1 + b1
    gemm_k<64,64,16,4,4,0><<<dim3(U_/64, (B_*S_)/64), 256>>>(encp, W1, b1, prep,
                                                             B_*S_, U_, U_, 0);

    // decoder (16 serial steps); logits batched at the end
    for (int t = 0; t < T_; t++) {
        float* hin  = hbase + (size_t)(t & 1) * B_ * U_;
        float* hout = hbase + (size_t)((t + 1) & 1) * B_ * U_;
        gemm_k<32,64,16,4,4,2><<<dim3(U_/64, 1, 8), 128>>>(hin, W2, nullptr, qpart,
                                                           B_, U_, U_, U_/8);
        attn_ctx<<<B_, 256>>>(b2, Va, bvp, Ed, teacher, t);
        gemm_k<32,64,16,4,4,2><<<dim3(G_/64, 1, 5), 128>>>(xcat, dWx, nullptr, gpart,
                                                           B_, G_, U_+E_, (U_+E_)/5);
        gru_gate_dec<<<128, 256>>>(db_in, db_rec, hout, t);
    }

    // logits = Hall @ Wf + bf  (rows t*32+b scattered to out[b][t][:])
    gemm_k<64,64,16,4,4,1><<<dim3((V_+63)/64, (T_*B_)/64), 256>>>(Hall, Wf, bf, logits_dst,
                                                                  T_*B_, V_, U_, 0);

    if (predI || predF) argmax_k<<<T_*B_, 256>>>(logits_dst, predI, predF, asFloat);
}

// round 3
// speedup vs baseline: 1.0895x; 1.0895x over previous
#include <cuda_runtime.h>
#include <cuda_bf16.h>
#include <math.h>
#include <stdint.h>

#define B_ 32
#define S_ 64
#define T_ 16
#define U_ 1024
#define E_ 256
#define V_ 20200
#define G_ 3072          /* 3*U */
#define VP_ 20224        /* V padded to 64 */

// ---------------- device scratch ----------------
__device__ __align__(16) float d_gxall[S_*B_*G_];           // [s][b][3072]
__device__ __align__(16) float d_hbuf[2][B_*U_];            // encoder hidden ping-pong
__device__ __align__(16) float d_hdec[B_*U_];               // decoder hidden
__device__ __align__(16) float d_enc[B_*S_*U_];             // encoded [b][s][u]
__device__ __align__(16) float d_pre[B_*S_*U_];             // W1(encoded)+b1
__device__ __align__(16) float d_q[B_*U_];                  // attention query
__device__ __align__(16) float d_gpart[8][B_*G_];           // split-K partials
__device__ __align__(16) float d_xcat[B_*(U_+E_)];          // [ctx, Ed[tok]]
__device__ __align__(16) float d_Hall[T_*B_*U_];            // decoder hiddens, rows t*32+b
__device__ __align__(16) float d_logits_alt[T_*B_*V_];
__device__ __align__(16) float d_WhP[U_*G_];                // eWh permuted cols (u*3+g)
__device__ __align__(16) float d_dWxP[(U_+E_)*G_];          // dWx permuted cols
// bf16 split operands
__device__ __align__(16) __nv_bfloat16 d_WfT3[(size_t)VP_*3072];
__device__ __align__(16) __nv_bfloat16 d_W1T3[1024*3072];
__device__ __align__(16) __nv_bfloat16 d_eWxT3[3072*768];
__device__ __align__(16) __nv_bfloat16 d_xembS[2048*768];
__device__ __align__(16) __nv_bfloat16 d_encS[(size_t)2048*3072];
__device__ __align__(16) __nv_bfloat16 d_HallS[512*3072];
__device__ unsigned int d_ctr[3*64];   // arrival counters (self-resetting)

__device__ __forceinline__ float sigm(float x) { return 1.f / (1.f + expf(-x)); }

// ---------------- setup kernels ----------------
// permute W[K][3072] columns: out[k][u*3+g] = W[k][g*1024+u]
__global__ void perm3(const float* __restrict__ W, float* __restrict__ out) {
    int idx = blockIdx.x * 256 + threadIdx.x;
    int k = idx / G_, c = idx - k * G_;
    int u = c / 3, g = c - u * 3;
    out[idx] = W[(size_t)k * G_ + g * U_ + u];
}

// embedding gather + bf16 split: row r=s*32+b -> [hi|lo|hi] over 3*256
__global__ void embed_split(const int* __restrict__ enc_in, const float* __restrict__ Ee) {
    int idx = blockIdx.x * 256 + threadIdx.x;
    int r = idx >> 8, e = idx & 255;
    int s = r >> 5, b = r & 31;
    float x = Ee[(size_t)enc_in[b * S_ + s] * E_ + e];
    __nv_bfloat16 hi = __float2bfloat16(x);
    __nv_bfloat16 lo = __float2bfloat16(x - __bfloat162float(hi));
    size_t base = (size_t)r * 768;
    d_xembS[base + e] = hi; d_xembS[base + 256 + e] = lo; d_xembS[base + 512 + e] = hi;
}

// A [M][K] fp32 -> [M][3K] bf16 = [hi|lo|hi]; K = 1<<kshift
__global__ void conv_splitA(const float* __restrict__ A, __nv_bfloat16* __restrict__ out, int kshift) {
    int idx = blockIdx.x * 256 + threadIdx.x;
    int K = 1 << kshift;
    int m = idx >> kshift, k = idx & (K - 1);
    float x = A[idx];
    __nv_bfloat16 hi = __float2bfloat16(x);
    __nv_bfloat16 lo = __float2bfloat16(x - __bfloat162float(hi));
    size_t base = (size_t)m * 3 * K;
    out[base + k] = hi; out[base + K + k] = lo; out[base + 2 * K + k] = hi;
}

// W [K][N] fp32 -> out [N][3K] bf16 = [hi|hi|lo] per row
__global__ void conv_splitB_T(const float* __restrict__ W, __nv_bfloat16* __restrict__ out,
                              int K, int N) {
    __shared__ float tile[32][33];
    int n0 = blockIdx.x * 32, k0 = blockIdx.y * 32;
    int tx = threadIdx.x, ty = threadIdx.y;            // (32, 8)
#pragma unroll
    for (int i = 0; i < 32; i += 8) {
        int k = k0 + ty + i, n = n0 + tx;
        tile[ty + i][tx] = (n < N) ? W[(size_t)k * N + n] : 0.f;
    }
    __syncthreads();
    const int K3 = 3 * K;
#pragma unroll
    for (int i = 0; i < 32; i += 8) {
        int n = n0 + ty + i, k = k0 + tx;
        if (n < N) {
            float x = tile[tx][ty + i];
            __nv_bfloat16 hi = __float2bfloat16(x);
            __nv_bfloat16 lo = __float2bfloat16(x - __bfloat162float(hi));
            size_t base = (size_t)n * K3;
            out[base + k] = hi; out[base + K + k] = hi; out[base + 2 * K + k] = lo;
        }
    }
}

// ---------------- tensor-core bf16 GEMM ----------------
__device__ __forceinline__ void mma_bf16(float* c, const uint32_t* a, const uint32_t* b) {
    asm volatile("mma.sync.aligned.m16n8k16.row.col.f32.bf16.bf16.f32 "
        "{%0,%1,%2,%3},{%4,%5,%6,%7},{%8,%9},{%0,%1,%2,%3};"
        : "+f"(c[0]), "+f"(c[1]), "+f"(c[2]), "+f"(c[3])
        : "r"(a[0]), "r"(a[1]), "r"(a[2]), "r"(a[3]), "r"(b[0]), "r"(b[1]));
}
__device__ __forceinline__ void ldsm_x4(uint32_t* r, uint32_t addr) {
    asm volatile("ldmatrix.sync.aligned.m8n8.x4.shared.b16 {%0,%1,%2,%3}, [%4];"
        : "=r"(r[0]), "=r"(r[1]), "=r"(r[2]), "=r"(r[3]) : "r"(addr));
}
__device__ __forceinline__ void ldsm_x2(uint32_t* r, uint32_t addr) {
    asm volatile("ldmatrix.sync.aligned.m8n8.x2.shared.b16 {%0,%1}, [%2];"
        : "=r"(r[0]), "=r"(r[1]) : "r"(addr));
}

// C = A'[M,K3] @ Bt'[N,K3]^T + bias ; tile BM=128 BN=64 BK=32, 256 thr (4m x 2n warps)
// MODE 0: C[gm*NP+gc]; MODE 1: logits scatter gm=t*32+b -> row b*16+t, stride Nreal
template<int MODE>
__global__ __launch_bounds__(256) void gemm_bf16(
    const __nv_bfloat16* __restrict__ A, const __nv_bfloat16* __restrict__ Bt,
    const float* __restrict__ bias, float* __restrict__ C,
    int NP, int Nreal, int K3)
{
    __shared__ __nv_bfloat16 As[2][128 * 40];
    __shared__ __nv_bfloat16 Bs[2][64 * 40];
    const int tid = threadIdx.x;
    const int wid = tid >> 5, lane = tid & 31;
    const int gid = lane >> 2, tig = lane & 3;
    const int wm = wid & 3, wn = wid >> 2;
    const int m0 = blockIdx.y * 128, n0 = blockIdx.x * 64;

    const uint32_t asBase = (uint32_t)__cvta_generic_to_shared(&As[0][0]);
    const uint32_t bsBase = (uint32_t)__cvta_generic_to_shared(&Bs[0][0]);
    const int lquad = lane >> 3, l7 = lane & 7, l15 = lane & 15;
    const uint32_t aLane = (uint32_t)((((lquad & 1) * 8 + l7) * 80) + (lquad >> 1) * 16);
    const uint32_t bLane = (uint32_t)(((l15 & 7) * 80) + ((l15 >> 3) & 1) * 16);

    float acc[2][4][4] = {};
    const int nkt = K3 >> 5;

    auto ldglobal = [&](int kt, int buf) {
#pragma unroll
        for (int i = 0; i < 2; i++) {
            int u4 = tid + i * 256;
            int row = u4 >> 2, c4 = u4 & 3;
            *(uint4*)&As[buf][row * 40 + c4 * 8] =
                *(const uint4*)&A[(size_t)(m0 + row) * K3 + kt * 32 + c4 * 8];
        }
        {
            int row = tid >> 2, c4 = tid & 3;
            *(uint4*)&Bs[buf][row * 40 + c4 * 8] =
                *(const uint4*)&Bt[(size_t)(n0 + row) * K3 + kt * 32 + c4 * 8];
        }
    };

    ldglobal(0, 0);
    __syncthreads();
    for (int kt = 0; kt < nkt; kt++) {
        const int buf = kt & 1;
        if (kt + 1 < nkt) ldglobal(kt + 1, buf ^ 1);
#pragma unroll
        for (int ks = 0; ks < 2; ks++) {
            uint32_t a[2][4], b[4][2];
#pragma unroll
            for (int mi = 0; mi < 2; mi++)
                ldsm_x4(a[mi], asBase + (uint32_t)(buf * 128 * 80) +
                               (uint32_t)((wm * 32 + mi * 16) * 80 + ks * 32) + aLane);
#pragma unroll
            for (int ni = 0; ni < 4; ni++)
                ldsm_x2(b[ni], bsBase + (uint32_t)(buf * 64 * 80) +
                               (uint32_t)((wn * 32 + ni * 8) * 80 + ks * 32) + bLane);
#pragma unroll
            for (int mi = 0; mi < 2; mi++)
#pragma unroll
                for (int ni = 0; ni < 4; ni++)
                    mma_bf16(acc[mi][ni], a[mi], b[ni]);
        }
        __syncthreads();
    }

#pragma unroll
    for (int mi = 0; mi < 2; mi++)
#pragma unroll
        for (int ni = 0; ni < 4; ni++) {
            int gm0 = m0 + wm * 32 + mi * 16 + gid;
            int gc0 = n0 + wn * 32 + ni * 8 + tig * 2;
#pragma unroll
            for (int e = 0; e < 4; e++) {
                int gm = gm0 + (e >> 1) * 8;
                int gc = gc0 + (e & 1);
                float v = acc[mi][ni][e];
                if (MODE == 1) {
                    if (gc < Nreal) {
                        int bb = gm & 31, tt = gm >> 5;
                        C[(size_t)(bb * T_ + tt) * Nreal + gc] = v + bias[gc];
                    }
                } else {
                    C[(size_t)gm * NP + gc] = v + bias[gc];
                }
            }
        }
}

// ---------------- fused recurrence step: split-K GEMM + last-block gate fixup ----
// BM=32, BK=16, 128 threads (TX=16, TY=8, TM=4).
// GATE 0: q = h@W2 + b2 -> qout    GATE 1: encoder GRU    GATE 2: decoder GRU (h0=0)
template<int BN, int TN, int NKC, int GATE>
__global__ __launch_bounds__(128) void step_gemm(
    const float* __restrict__ A, const float* __restrict__ Bm,
    const float* __restrict__ xb, const float* __restrict__ hb,
    const float* __restrict__ hin, float* __restrict__ hout,
    float* __restrict__ extra, float* __restrict__ part,
    float* __restrict__ qout, unsigned int* __restrict__ ctr,
    int N, int K)
{
    __shared__ float As[16][32];
    __shared__ float Bs[16][BN];
    __shared__ int doneflag;
    const int tid = threadIdx.x;
    const int tx = tid & 15, ty = tid >> 4;
    const int n0 = blockIdx.x * BN;
    const int z = blockIdx.z;
    const int k0 = z * NKC * 16;

    float acc[4][TN];
#pragma unroll
    for (int i = 0; i < 4; i++)
#pragma unroll
        for (int j = 0; j < TN; j++) acc[i][j] = 0.f;

    for (int kt = 0; kt < NKC; kt++) {
#pragma unroll
        for (int ii = tid; ii < 512; ii += 128) {
            int k = ii & 15, m = ii >> 4;
            As[k][m] = A[(size_t)m * K + k0 + kt * 16 + k];
        }
        for (int ii = tid; ii < 16 * BN; ii += 128) {
            int k = ii / BN, n = ii - k * BN;
            Bs[k][n] = Bm[(size_t)(k0 + kt * 16 + k) * N + n0 + n];
        }
        __syncthreads();
#pragma unroll
        for (int kk = 0; kk < 16; kk++) {
            float4 av = *reinterpret_cast<const float4*>(&As[kk][ty * 4]);
            float a[4] = {av.x, av.y, av.z, av.w};
#pragma unroll
            for (int j = 0; j < TN; j++) {
                float bv = Bs[kk][tx * TN + j];
#pragma unroll
                for (int i = 0; i < 4; i++) acc[i][j] += a[i] * bv;
            }
        }
        __syncthreads();
    }
    // write partials
#pragma unroll
    for (int i = 0; i < 4; i++) {
        int gm = ty * 4 + i;
#pragma unroll
        for (int j = 0; j < TN; j++)
            part[((size_t)(z * 32 + gm)) * N + n0 + tx * TN + j] = acc[i][j];
    }
    __threadfence();
    __syncthreads();
    if (tid == 0) {
        unsigned int prev = atomicAdd(&ctr[blockIdx.x], 1u);
        doneflag = (prev == 7u);
        if (prev == 7u) ctr[blockIdx.x] = 0u;   // self-reset for next launch
    }
    __syncthreads();
    if (!doneflag) return;
    __threadfence();   // acquire: all partials visible

    if (GATE == 0) {
        // q[b][n] = sum_z part + b2[n]
#pragma unroll
        for (int i = 0; i < 16; i++) {
            int idx = tid + i * 128;           // 2048 = 64 cols x 32 b
            int b = idx & 31, nl = idx >> 5;
            int n = n0 + nl;
            float s = 0.f;
#pragma unroll
            for (int zz = 0; zz < 8; zz++) s += part[((size_t)(zz * 32 + b)) * N + n];
            qout[b * U_ + n] = s + hb[n];
        }
    } else {
        const int u0 = n0 / 3;                 // BN=48 -> 16 u's
#pragma unroll
        for (int i = 0; i < 4; i++) {
            int idx = tid + i * 128;           // 512 = 16 u x 32 b
            int b = idx & 31, ul = idx >> 5;
            int u = u0 + ul;
            float g[3];
#pragma unroll
            for (int gg = 0; gg < 3; gg++) {
                float s = 0.f;
#pragma unroll
                for (int zz = 0; zz < 8; zz++)
                    s += part[((size_t)(zz * 32 + b)) * N + n0 + ul * 3 + gg];
                g[gg] = s;
            }
            float h;
            if (GATE == 1) {
                const float* gx = xb + (size_t)b * G_;
                float zg = sigm(gx[u] + g[0] + hb[u]);
                float rg = sigm(gx[U_ + u] + g[1] + hb[U_ + u]);
                float cg = tanhf(gx[2 * U_ + u] + rg * (g[2] + hb[2 * U_ + u]));
                h = zg * hin[b * U_ + u] + (1.f - zg) * cg;
                hout[b * U_ + u] = h;
                extra[(size_t)b * (S_ * U_) + u] = h;      // extra = d_enc + s*U_
            } else {
                float zg = sigm(g[0] + xb[u] + hb[u]);
                float rg = sigm(g[1] + xb[U_ + u] + hb[U_ + u]);
                float cg = tanhf(g[2] + xb[2 * U_ + u] + rg * hb[2 * U_ + u]);
                h = (1.f - zg) * cg;
                hout[b * U_ + u] = h;                       // d_hdec
                extra[(size_t)b * U_ + u] = h;              // d_Hall + t*B*U
            }
        }
    }
}

// ---------------- attention + context + embed concat ----------------
__global__ void attn_ctx(const float* __restrict__ Va, const float* __restrict__ bvp,
                         const float* __restrict__ Ed, const int* __restrict__ teacher, int t)
{
    const int b = blockIdx.x, tid = threadIdx.x;
    __shared__ float qs[U_];
    __shared__ float sc[S_];
    __shared__ float inv_s;

    for (int u = tid; u < U_; u += 256) qs[u] = d_q[b * U_ + u];
    __syncthreads();

    const int w = tid >> 5, lane = tid & 31;
    for (int s = w; s < S_; s += 8) {
        const float* pr = d_pre + (size_t)b * (S_ * U_) + (size_t)s * U_;
        float p = 0.f;
        for (int u = lane; u < U_; u += 32) p += tanhf(pr[u] + qs[u]) * Va[u];
#pragma unroll
        for (int o = 16; o > 0; o >>= 1) p += __shfl_xor_sync(0xffffffffu, p, o);
        if (lane == 0) sc[s] = p + bvp[0];
    }
    __syncthreads();

    if (tid == 0) {
        float m = sc[0];
        for (int s = 1; s < S_; s++) m = fmaxf(m, sc[s]);
        float sum = 0.f;
        for (int s = 0; s < S_; s++) { float e = expf(sc[s] - m); sc[s] = e; sum += e; }
        inv_s = 1.f / sum;
    }
    __syncthreads();

    const float inv = inv_s;
    for (int u = tid; u < U_; u += 256) {
        float a = 0.f;
        const float* eb = d_enc + (size_t)b * (S_ * U_) + u;
#pragma unroll 8
        for (int s = 0; s < S_; s++) a += sc[s] * eb[(size_t)s * U_];
        d_xcat[(size_t)b * (U_ + E_) + u] = a * inv;
    }
    const int tok = teacher[b * T_ + t];
    if (tid < E_) d_xcat[(size_t)b * (U_ + E_) + U_ + tid] = Ed[(size_t)tok * E_ + tid];
}

// ---------------- argmax ----------------
__global__ void argmax_k(const float* __restrict__ logits, long long* outI, float* outF, int asFloat)
{
    const int row = blockIdx.x;
    const float* p = logits + (size_t)row * V_;
    const int tid = threadIdx.x;
    float best = -INFINITY; int bi = 0;
    for (int v = tid; v < V_; v += 256) {
        float val = p[v];
        if (val > best) { best = val; bi = v; }
    }
    __shared__ float bvs[256]; __shared__ int bis[256];
    bvs[tid] = best; bis[tid] = bi;
    __syncthreads();
    for (int st = 128; st > 0; st >>= 1) {
        if (tid < st) {
            float ov = bvs[tid + st]; int oi = bis[tid + st];
            if (ov > bvs[tid] || (ov == bvs[tid] && oi < bis[tid])) { bvs[tid] = ov; bis[tid] = oi; }
        }
        __syncthreads();
    }
    if (tid == 0) {
        if (asFloat) outF[row] = (float)bis[0];
        else         outI[row] = (long long)bis[0];
    }
}

// ---------------- launcher ----------------
static float* symaddr(const void* sym) {
    void* p = nullptr;
    cudaGetSymbolAddress(&p, sym);
    return (float*)p;
}

extern "C" void kernel_launch(void* const* d_in, const int* in_sizes, int n_in,
                              void* d_out, int out_size)
{
    const int s0 = (n_in >= 22) ? 4 : 2;
    const int*   enc_in  = (const int*)d_in[0];
    const int*   teacher = (const int*)d_in[1];
    const float* Ee      = (const float*)d_in[s0 + 0];
    const float* eWx     = (const float*)d_in[s0 + 1];
    const float* eWh     = (const float*)d_in[s0 + 2];
    const float* eb_in   = (const float*)d_in[s0 + 3];
    const float* eb_rec  = (const float*)d_in[s0 + 4];
    const float* Ed      = (const float*)d_in[s0 + 5];
    const float* dWx     = (const float*)d_in[s0 + 6];
    const float* db_in   = (const float*)d_in[s0 + 8];
    const float* db_rec  = (const float*)d_in[s0 + 9];
    const float* W1      = (const float*)d_in[s0 + 10];
    const float* b1      = (const float*)d_in[s0 + 11];
    const float* W2      = (const float*)d_in[s0 + 12];
    const float* b2      = (const float*)d_in[s0 + 13];
    const float* Va      = (const float*)d_in[s0 + 14];
    const float* bvp     = (const float*)d_in[s0 + 15];
    const float* Wf      = (const float*)d_in[s0 + 16];
    const float* bf      = (const float*)d_in[s0 + 17];

    float* hbase = symaddr(d_hbuf);
    float* hdec  = symaddr(d_hdec);
    float* encp  = symaddr(d_enc);
    float* prep  = symaddr(d_pre);
    float* qp    = symaddr(d_q);
    float* gpart = symaddr(d_gpart);
    float* xcat  = symaddr(d_xcat);
    float* Hall  = symaddr(d_Hall);
    float* lalt  = symaddr(d_logits_alt);
    float* gxall = symaddr(d_gxall);
    float* WhP   = symaddr(d_WhP);
    float* dWxP  = symaddr(d_dWxP);
    unsigned int* ctr; { void* p; cudaGetSymbolAddress(&p, d_ctr); ctr = (unsigned int*)p; }
    __nv_bfloat16* WfT3;  { void* p; cudaGetSymbolAddress(&p, d_WfT3);  WfT3  = (__nv_bfloat16*)p; }
    __nv_bfloat16* W1T3;  { void* p; cudaGetSymbolAddress(&p, d_W1T3);  W1T3  = (__nv_bfloat16*)p; }
    __nv_bfloat16* eWxT3; { void* p; cudaGetSymbolAddress(&p, d_eWxT3); eWxT3 = (__nv_bfloat16*)p; }
    __nv_bfloat16* xembS; { void* p; cudaGetSymbolAddress(&p, d_xembS); xembS = (__nv_bfloat16*)p; }
    __nv_bfloat16* encS;  { void* p; cudaGetSymbolAddress(&p, d_encS);  encS  = (__nv_bfloat16*)p; }
    __nv_bfloat16* HallS; { void* p; cudaGetSymbolAddress(&p, d_HallS); HallS = (__nv_bfloat16*)p; }

    // output convention
    const long long LOGN = (long long)B_ * T_ * V_;
    float* logits_dst = (float*)d_out;
    long long* predI = nullptr; float* predF = nullptr; int asFloat = 0;
    if ((long long)out_size == LOGN + 512) { predF = (float*)d_out + LOGN; asFloat = 1; }
    else if ((long long)out_size == LOGN + 1024) { predI = (long long*)((float*)d_out + LOGN); }
    else if (out_size == 512) { logits_dst = lalt; predI = (long long*)d_out; }

    cudaMemsetAsync(hbase, 0, (size_t)B_ * U_ * sizeof(float));

    // weight prep (every call: inputs may change)
    perm3<<<U_*G_/256, 256>>>(eWh, WhP);
    perm3<<<(U_+E_)*G_/256, 256>>>(dWx, dWxP);
    conv_splitB_T<<<dim3(G_/32, E_/32), dim3(32,8)>>>(eWx, eWxT3, E_, G_);
    conv_splitB_T<<<dim3(U_/32, U_/32), dim3(32,8)>>>(W1, W1T3, U_, U_);
    conv_splitB_T<<<dim3((V_+31)/32, U_/32), dim3(32,8)>>>(Wf, WfT3, U_, V_);

    // encoder front: embed + gx (all steps, tensor cores)
    embed_split<<<2048, 256>>>(enc_in, Ee);
    gemm_bf16<0><<<dim3(G_/64, (S_*B_)/128), 256>>>(xembS, eWxT3, eb_in, gxall, G_, G_, 768);

    // encoder recurrence: one fused launch per step
    for (int s = 0; s < S_; s++) {
        float* hin  = hbase + (size_t)(s & 1) * B_ * U_;
        float* hout = hbase + (size_t)((s + 1) & 1) * B_ * U_;
        step_gemm<48,3,8,1><<<dim3(G_/48, 1, 8), 128>>>(
            hin, WhP, gxall + (size_t)s * B_ * G_, eb_rec,
            hin, hout, encp + (size_t)s * U_, gpart, nullptr, ctr, G_, U_);
    }

    // pre_enc = encoded @ W1 + b1 (tensor cores)
    conv_splitA<<<(B_*S_*U_)/256, 256>>>(encp, encS, 10);
    gemm_bf16<0><<<dim3(U_/64, (B_*S_)/128), 256>>>(encS, W1T3, b1, prep, U_, U_, 3072);

    // decoder: 3 launches per step
    for (int t = 0; t < T_; t++) {
        const float* hd = (t == 0) ? hbase : hdec;
        step_gemm<64,4,8,0><<<dim3(U_/64, 1, 8), 128>>>(
            hd, W2, nullptr, b2, nullptr, nullptr, nullptr, gpart, qp, ctr + 64, U_, U_);
        attn_ctx<<<B_, 256>>>(Va, bvp, Ed, teacher, t);
        step_gemm<48,3,10,2><<<dim3(G_/48, 1, 8), 128>>>(
            xcat, dWxP, db_in, db_rec, nullptr, hdec,
            Hall + (size_t)t * B_ * U_, gpart, nullptr, ctr + 128, G_, U_ + E_);
    }

    // logits = Hall @ Wf + bf (tensor cores, scatter epilogue)
    conv_splitA<<<(T_*B_*U_)/256, 256>>>(Hall, HallS, 10);
    gemm_bf16<1><<<dim3(VP_/64, (T_*B_)/128), 256>>>(HallS, WfT3, bf, logits_dst, 0, V_, 3072);

    if (predI || predF) argmax_k<<<T_*B_, 256>>>(logits_dst, predI, predF, asFloat);
}